// round 7
// baseline (speedup 1.0000x reference)
#include <cuda_runtime.h>
#include <cuda_bf16.h>
#include <cstdint>

// Problem constants: B=4, N=256, D=128, M=128, C=128
#define BB 4
#define NN 256
#define DD 128
#define MM 128
#define CC 128

// Scratch (device globals — no allocation allowed)
// Both PRE-SCALED by 0.5 so hx = g_pi + g_pjb = pre/2, silu(pre)=hx+hx*tanh(hx)
__device__ float g_pi[BB * NN * MM];
__device__ float g_pjb[BB * NN * MM];
__device__ float g_W2c[MM * MM];   // W2 @ Wc1
__device__ float g_b2c[MM];        // b2 @ Wc1

__device__ __forceinline__ float tanh_approx(float x) {
    float y;
    asm("tanh.approx.f32 %0, %1;" : "=f"(y) : "f"(x));
    return y;
}
__device__ __forceinline__ float siluf(float x) {
    return __fdividef(x, 1.0f + __expf(-x));
}

__device__ __forceinline__ void cp16(unsigned int dst, const float* src) {
    asm volatile("cp.async.cg.shared.global [%0], [%1], 16;" :: "r"(dst), "l"(src));
}
#define CP_COMMIT()   asm volatile("cp.async.commit_group;")
#define CP_WAIT(n)    asm volatile("cp.async.wait_group %0;" :: "n"(n))

// ---------------------------------------------------------------------------
// Prep kernel: 321 blocks x 256 threads.
// ---------------------------------------------------------------------------
__global__ void __launch_bounds__(256) prep_kernel(
    const float* __restrict__ h,
    const float* __restrict__ W1a,
    const float* __restrict__ W1b,
    const float* __restrict__ b1,
    const float* __restrict__ W2,
    const float* __restrict__ b2,
    const float* __restrict__ Wc1)
{
    const int t = threadIdx.x;

    if (blockIdx.x < 256) {
        const int row0 = blockIdx.x * 4;
        const int col  = t & 127;
        const int rh   = (t >> 7) * 2;

        __shared__ float hsh[4][DD];
        #pragma unroll
        for (int k = 0; k < 2; k++) {
            int idx = k * 256 + t;
            hsh[idx >> 7][idx & 127] = h[(size_t)row0 * DD + idx];
        }
        __syncthreads();

        float a0 = 0.f, a1 = 0.f, p0 = 0.f, p1 = 0.f;
        #pragma unroll 8
        for (int d = 0; d < DD; d++) {
            const float wa = W1a[d * MM + col];
            const float wb = W1b[d * MM + col];
            const float h0 = hsh[rh][d];
            const float h1 = hsh[rh + 1][d];
            a0 = fmaf(h0, wa, a0);
            a1 = fmaf(h1, wa, a1);
            p0 = fmaf(h0, wb, p0);
            p1 = fmaf(h1, wb, p1);
        }
        const float bb = b1[col];
        const int r0 = row0 + rh;
        g_pi[(size_t)r0 * MM + col]        = 0.5f * a0;
        g_pi[(size_t)(r0 + 1) * MM + col]  = 0.5f * a1;
        g_pjb[(size_t)r0 * MM + col]       = 0.5f * (p0 + bb);
        g_pjb[(size_t)(r0 + 1) * MM + col] = 0.5f * (p1 + bb);
    } else if (blockIdx.x < 320) {
        const int m  = (blockIdx.x - 256) * 2 + (t >> 7);
        const int k  = t & 127;

        __shared__ float w2row[2][MM];
        w2row[t >> 7][k] = W2[m * MM + k];
        __syncthreads();

        float v0 = 0.f, v1 = 0.f;
        #pragma unroll 8
        for (int l = 0; l < MM; l += 2) {
            v0 = fmaf(w2row[t >> 7][l],     Wc1[l * MM + k],       v0);
            v1 = fmaf(w2row[t >> 7][l + 1], Wc1[(l + 1) * MM + k], v1);
        }
        g_W2c[m * MM + k] = v0 + v1;
    } else {
        if (t < MM) {
            float v = 0.f;
            #pragma unroll 8
            for (int l = 0; l < MM; l++)
                v = fmaf(b2[l], Wc1[l * MM + t], v);
            g_b2c[t] = v;
        }
    }
}

// ---------------------------------------------------------------------------
// Main kernel: one block per (b,i). 256 threads = 8 warps.
// Warp w handles j = w, w+8, ..., w+248 (32 rows). Per-warp cp.async ring
// (6 slots x 512B), per-thread commit groups, 4 rows in flight, no barriers.
// ---------------------------------------------------------------------------
__global__ void __launch_bounds__(256) main_kernel(
    const float* __restrict__ adj,
    const float* __restrict__ bc1,
    const float* __restrict__ Wc2,
    const float* __restrict__ bc2,
    float* __restrict__ out)
{
    const int bi = blockIdx.x;          // 0..1023
    const int b  = bi >> 8;
    const int i  = bi & (NN - 1);
    const int t  = threadIdx.x;

    __shared__ float4 ring[8][6][32];   // warp, slot, lane  = 24KB
    __shared__ float adj_sh[NN];
    __shared__ float accsh[8][MM];
    __shared__ float wsum[8];
    __shared__ float sacc[MM];
    __shared__ float parts[2][MM];
    __shared__ float shid[MM];

    // Load adj row; diagonal-masked copy; full-row sum
    const float* adjrow = adj + (size_t)bi * NN;
    float av = adjrow[t];
    adj_sh[t] = (t == i) ? 0.0f : av;
    const float adj_ii = adjrow[i];
    #pragma unroll
    for (int o = 16; o; o >>= 1) av += __shfl_xor_sync(0xFFFFFFFFu, av, o);
    if ((t & 31) == 0) wsum[t >> 5] = av;
    __syncthreads();

    float sum_all = 0.f;
    #pragma unroll
    for (int g = 0; g < 8; g++) sum_all += wsum[g];
    const float S     = sum_all - adj_ii;
    const float inv_d = __fdividef(1.0f, fmaxf(sum_all, 1.0f));

    const int lane = t & 31;
    const int w    = t >> 5;            // warp id = j-lane 0..7

    const float4 pi4 = *reinterpret_cast<const float4*>(g_pi + (size_t)bi * MM + lane * 4);
    // warp w's rows: j = w + 8*jo; each lane copies 16B at lane*4 floats
    const float* base = g_pjb + (size_t)b * NN * MM + (size_t)w * MM + lane * 4;

    unsigned int ring_lane = (unsigned int)__cvta_generic_to_shared(&ring[w][0][lane]);
    const unsigned int SLOT_STRIDE = 32 * sizeof(float4);   // 512B

    float4 acc = make_float4(0.f, 0.f, 0.f, 0.f);

    // Prologue: 4 rows in flight (rows jo = 0..3)
    #pragma unroll
    for (int r = 0; r < 4; r++) {
        cp16(ring_lane + r * SLOT_STRIDE, base + (size_t)(8 * r) * MM);
        CP_COMMIT();
    }

    // Steady state: 28 iterations, wait_group 3 => group jo complete
    #pragma unroll 4
    for (int jo = 0; jo < 28; jo++) {
        CP_WAIT(3);
        const float4 v = ring[w][jo % 6][lane];
        const float wj = adj_sh[w + 8 * jo];
        float hx0 = pi4.x + v.x;
        float hx1 = pi4.y + v.y;
        float hx2 = pi4.z + v.z;
        float hx3 = pi4.w + v.w;
        float s0 = fmaf(hx0, tanh_approx(hx0), hx0);
        float s1 = fmaf(hx1, tanh_approx(hx1), hx1);
        float s2 = fmaf(hx2, tanh_approx(hx2), hx2);
        float s3 = fmaf(hx3, tanh_approx(hx3), hx3);
        acc.x = fmaf(wj, s0, acc.x);
        acc.y = fmaf(wj, s1, acc.y);
        acc.z = fmaf(wj, s2, acc.z);
        acc.w = fmaf(wj, s3, acc.w);
        // issue row jo+4 into slot (jo+4)%6 (consumed at jo-2, LDS retired)
        cp16(ring_lane + ((jo + 4) % 6) * SLOT_STRIDE, base + (size_t)(8 * (jo + 4)) * MM);
        CP_COMMIT();
    }

    // Drain: all groups complete, consume rows 28..31
    CP_WAIT(0);
    #pragma unroll
    for (int jo = 28; jo < 32; jo++) {
        const float4 v = ring[w][jo % 6][lane];
        const float wj = adj_sh[w + 8 * jo];
        float hx0 = pi4.x + v.x;
        float hx1 = pi4.y + v.y;
        float hx2 = pi4.z + v.z;
        float hx3 = pi4.w + v.w;
        float s0 = fmaf(hx0, tanh_approx(hx0), hx0);
        float s1 = fmaf(hx1, tanh_approx(hx1), hx1);
        float s2 = fmaf(hx2, tanh_approx(hx2), hx2);
        float s3 = fmaf(hx3, tanh_approx(hx3), hx3);
        acc.x = fmaf(wj, s0, acc.x);
        acc.y = fmaf(wj, s1, acc.y);
        acc.z = fmaf(wj, s2, acc.z);
        acc.w = fmaf(wj, s3, acc.w);
    }

    *reinterpret_cast<float4*>(&accsh[w][lane * 4]) = acc;
    __syncthreads();

    if (t < MM) {
        float v = 0.f;
        #pragma unroll
        for (int g = 0; g < 8; g++) v += accsh[g][t];
        sacc[t] = v;
    }
    __syncthreads();

    // ---- epilogue: 2 matvecs (W2@Wc1 pre-folded) ----
    const int col  = t & (MM - 1);
    const int half = t >> 7;
    const int m0   = half * (MM / 2);

    {
        float v0 = 0.f, v1 = 0.f, v2 = 0.f, v3 = 0.f;
        #pragma unroll 4
        for (int m2 = m0; m2 < m0 + MM / 2; m2 += 4) {
            v0 = fmaf(sacc[m2],     g_W2c[m2 * MM + col],       v0);
            v1 = fmaf(sacc[m2 + 1], g_W2c[(m2 + 1) * MM + col], v1);
            v2 = fmaf(sacc[m2 + 2], g_W2c[(m2 + 2) * MM + col], v2);
            v3 = fmaf(sacc[m2 + 3], g_W2c[(m2 + 3) * MM + col], v3);
        }
        parts[half][col] = (v0 + v1) + (v2 + v3);
    }
    __syncthreads();
    if (t < MM) {
        float u = fmaf(parts[0][t] + parts[1][t] + S * g_b2c[t], inv_d, bc1[t]);
        shid[t] = siluf(u);
    }
    __syncthreads();

    {
        float v0 = (half == 0) ? bc2[col] : 0.0f, v1 = 0.f, v2 = 0.f, v3 = 0.f;
        #pragma unroll 4
        for (int m2 = m0; m2 < m0 + MM / 2; m2 += 4) {
            v0 = fmaf(shid[m2],     Wc2[m2 * CC + col],       v0);
            v1 = fmaf(shid[m2 + 1], Wc2[(m2 + 1) * CC + col], v1);
            v2 = fmaf(shid[m2 + 2], Wc2[(m2 + 2) * CC + col], v2);
            v3 = fmaf(shid[m2 + 3], Wc2[(m2 + 3) * CC + col], v3);
        }
        parts[half][col] = (v0 + v1) + (v2 + v3);
    }
    __syncthreads();
    if (t < CC) out[(size_t)bi * CC + t] = parts[0][t] + parts[1][t];
}

// ---------------------------------------------------------------------------
// Launch
// ---------------------------------------------------------------------------
extern "C" void kernel_launch(void* const* d_in, const int* in_sizes, int n_in,
                              void* d_out, int out_size)
{
    const float* h   = (const float*)d_in[0];
    const float* adj = (const float*)d_in[1];
    const float* W1a = (const float*)d_in[2];
    const float* W1b = (const float*)d_in[3];
    const float* b1  = (const float*)d_in[4];
    const float* W2  = (const float*)d_in[5];
    const float* b2  = (const float*)d_in[6];
    const float* Wc1 = (const float*)d_in[7];
    const float* bc1 = (const float*)d_in[8];
    const float* Wc2 = (const float*)d_in[9];
    const float* bc2 = (const float*)d_in[10];
    float* out = (float*)d_out;

    prep_kernel<<<321, 256>>>(h, W1a, W1b, b1, W2, b2, Wc1);
    main_kernel<<<BB * NN, 256>>>(adj, bc1, Wc2, bc2, out);
}

// round 8
// speedup vs baseline: 1.0797x; 1.0797x over previous
#include <cuda_runtime.h>
#include <cuda_bf16.h>
#include <cstdint>

// Problem constants: B=4, N=256, D=128, M=128, C=128
#define BB 4
#define NN 256
#define DD 128
#define MM 128
#define CC 128

// Scratch (device globals — no allocation allowed)
// Both PRE-SCALED by 0.5 so hx = g_pi + g_pjb = pre/2, silu(pre)=hx+hx*tanh(hx)
__device__ float g_pi[BB * NN * MM];
__device__ float g_pjb[BB * NN * MM];
__device__ float g_W2c[MM * MM];   // W2 @ Wc1
__device__ float g_b2c[MM];        // b2 @ Wc1

__device__ __forceinline__ float tanh_approx(float x) {
    float y;
    asm("tanh.approx.f32 %0, %1;" : "=f"(y) : "f"(x));
    return y;
}
__device__ __forceinline__ float siluf(float x) {
    return __fdividef(x, 1.0f + __expf(-x));
}

__device__ __forceinline__ void cp16(unsigned int dst, const float* src) {
    asm volatile("cp.async.cg.shared.global [%0], [%1], 16;" :: "r"(dst), "l"(src));
}
#define CP_COMMIT()   asm volatile("cp.async.commit_group;")
#define CP_WAIT(n)    asm volatile("cp.async.wait_group %0;" :: "n"(n))

// ---------------------------------------------------------------------------
// Prep kernel: 321 blocks x 256 threads.
// ---------------------------------------------------------------------------
__global__ void __launch_bounds__(256) prep_kernel(
    const float* __restrict__ h,
    const float* __restrict__ W1a,
    const float* __restrict__ W1b,
    const float* __restrict__ b1,
    const float* __restrict__ W2,
    const float* __restrict__ b2,
    const float* __restrict__ Wc1)
{
    const int t = threadIdx.x;

    if (blockIdx.x < 256) {
        const int row0 = blockIdx.x * 4;
        const int col  = t & 127;
        const int rh   = (t >> 7) * 2;

        __shared__ float hsh[4][DD];
        #pragma unroll
        for (int k = 0; k < 2; k++) {
            int idx = k * 256 + t;
            hsh[idx >> 7][idx & 127] = h[(size_t)row0 * DD + idx];
        }
        __syncthreads();

        float a0 = 0.f, a1 = 0.f, p0 = 0.f, p1 = 0.f;
        #pragma unroll 8
        for (int d = 0; d < DD; d++) {
            const float wa = W1a[d * MM + col];
            const float wb = W1b[d * MM + col];
            const float h0 = hsh[rh][d];
            const float h1 = hsh[rh + 1][d];
            a0 = fmaf(h0, wa, a0);
            a1 = fmaf(h1, wa, a1);
            p0 = fmaf(h0, wb, p0);
            p1 = fmaf(h1, wb, p1);
        }
        const float bb = b1[col];
        const int r0 = row0 + rh;
        g_pi[(size_t)r0 * MM + col]        = 0.5f * a0;
        g_pi[(size_t)(r0 + 1) * MM + col]  = 0.5f * a1;
        g_pjb[(size_t)r0 * MM + col]       = 0.5f * (p0 + bb);
        g_pjb[(size_t)(r0 + 1) * MM + col] = 0.5f * (p1 + bb);
    } else if (blockIdx.x < 320) {
        const int m  = (blockIdx.x - 256) * 2 + (t >> 7);
        const int k  = t & 127;

        __shared__ float w2row[2][MM];
        w2row[t >> 7][k] = W2[m * MM + k];
        __syncthreads();

        float v0 = 0.f, v1 = 0.f;
        #pragma unroll 8
        for (int l = 0; l < MM; l += 2) {
            v0 = fmaf(w2row[t >> 7][l],     Wc1[l * MM + k],       v0);
            v1 = fmaf(w2row[t >> 7][l + 1], Wc1[(l + 1) * MM + k], v1);
        }
        g_W2c[m * MM + k] = v0 + v1;
    } else {
        if (t < MM) {
            float v = 0.f;
            #pragma unroll 8
            for (int l = 0; l < MM; l++)
                v = fmaf(b2[l], Wc1[l * MM + t], v);
            g_b2c[t] = v;
        }
    }
}

// ---------------------------------------------------------------------------
// Main kernel: one block per (b,i). 256 threads = 8 warps.
// Warp w handles j = w, w+8, ..., w+248 (32 rows). Per-warp cp.async ring
// (6 slots x 512B), FULLY UNROLLED so all slot indices and address offsets
// are compile-time immediates (no ALU tax).
// ---------------------------------------------------------------------------
__global__ void __launch_bounds__(256) main_kernel(
    const float* __restrict__ adj,
    const float* __restrict__ bc1,
    const float* __restrict__ Wc2,
    const float* __restrict__ bc2,
    float* __restrict__ out)
{
    const int bi = blockIdx.x;          // 0..1023
    const int b  = bi >> 8;
    const int i  = bi & (NN - 1);
    const int t  = threadIdx.x;

    __shared__ float4 ring[8][6][32];   // warp, slot, lane  = 24KB
    __shared__ float adj_sh[NN];
    __shared__ float accsh[8][MM];
    __shared__ float wsum[8];
    __shared__ float sacc[MM];
    __shared__ float parts[2][MM];
    __shared__ float shid[MM];

    // Load adj row; diagonal-masked copy; full-row sum
    const float* adjrow = adj + (size_t)bi * NN;
    float av = adjrow[t];
    adj_sh[t] = (t == i) ? 0.0f : av;
    const float adj_ii = adjrow[i];
    #pragma unroll
    for (int o = 16; o; o >>= 1) av += __shfl_xor_sync(0xFFFFFFFFu, av, o);
    if ((t & 31) == 0) wsum[t >> 5] = av;
    __syncthreads();

    float sum_all = 0.f;
    #pragma unroll
    for (int g = 0; g < 8; g++) sum_all += wsum[g];
    const float S     = sum_all - adj_ii;
    const float inv_d = __fdividef(1.0f, fmaxf(sum_all, 1.0f));

    const int lane = t & 31;
    const int w    = t >> 5;            // warp id = j-lane 0..7

    const float4 pi4 = *reinterpret_cast<const float4*>(g_pi + (size_t)bi * MM + lane * 4);
    // warp w's rows: j = w + 8*jo; each lane copies 16B at lane*4 floats
    const float* base = g_pjb + (size_t)b * NN * MM + (size_t)w * MM + lane * 4;

    const unsigned int ring_lane =
        (unsigned int)__cvta_generic_to_shared(&ring[w][0][lane]);
    const float4* ring_rd = &ring[w][0][lane];   // slot stride = 32 float4
    const float*  adj_w   = adj_sh + w;          // row weight at adj_w[8*jo]

    float4 acc = make_float4(0.f, 0.f, 0.f, 0.f);

    // Prologue: 4 rows in flight (rows jo = 0..3)
    #pragma unroll
    for (int r = 0; r < 4; r++) {
        cp16(ring_lane + (unsigned int)(r * 32 * sizeof(float4)), base + 8 * r * MM);
        CP_COMMIT();
    }

    // Steady state: FULLY unrolled; slot = jo%6 and all offsets constant
    #pragma unroll
    for (int jo = 0; jo < 28; jo++) {
        CP_WAIT(3);
        const float4 v = ring_rd[(jo % 6) * 32];
        const float wj = adj_w[8 * jo];
        float hx0 = pi4.x + v.x;
        float hx1 = pi4.y + v.y;
        float hx2 = pi4.z + v.z;
        float hx3 = pi4.w + v.w;
        float s0 = fmaf(hx0, tanh_approx(hx0), hx0);
        float s1 = fmaf(hx1, tanh_approx(hx1), hx1);
        float s2 = fmaf(hx2, tanh_approx(hx2), hx2);
        float s3 = fmaf(hx3, tanh_approx(hx3), hx3);
        acc.x = fmaf(wj, s0, acc.x);
        acc.y = fmaf(wj, s1, acc.y);
        acc.z = fmaf(wj, s2, acc.z);
        acc.w = fmaf(wj, s3, acc.w);
        // issue row jo+4 into slot (jo+4)%6
        cp16(ring_lane + (unsigned int)(((jo + 4) % 6) * 32 * sizeof(float4)),
             base + 8 * (jo + 4) * MM);
        CP_COMMIT();
    }

    // Drain: all groups complete, consume rows 28..31
    CP_WAIT(0);
    #pragma unroll
    for (int jo = 28; jo < 32; jo++) {
        const float4 v = ring_rd[(jo % 6) * 32];
        const float wj = adj_w[8 * jo];
        float hx0 = pi4.x + v.x;
        float hx1 = pi4.y + v.y;
        float hx2 = pi4.z + v.z;
        float hx3 = pi4.w + v.w;
        float s0 = fmaf(hx0, tanh_approx(hx0), hx0);
        float s1 = fmaf(hx1, tanh_approx(hx1), hx1);
        float s2 = fmaf(hx2, tanh_approx(hx2), hx2);
        float s3 = fmaf(hx3, tanh_approx(hx3), hx3);
        acc.x = fmaf(wj, s0, acc.x);
        acc.y = fmaf(wj, s1, acc.y);
        acc.z = fmaf(wj, s2, acc.z);
        acc.w = fmaf(wj, s3, acc.w);
    }

    *reinterpret_cast<float4*>(&accsh[w][lane * 4]) = acc;
    __syncthreads();

    if (t < MM) {
        float v = 0.f;
        #pragma unroll
        for (int g = 0; g < 8; g++) v += accsh[g][t];
        sacc[t] = v;
    }
    __syncthreads();

    // ---- epilogue: 2 matvecs (W2@Wc1 pre-folded) ----
    const int col  = t & (MM - 1);
    const int half = t >> 7;
    const int m0   = half * (MM / 2);

    {
        float v0 = 0.f, v1 = 0.f, v2 = 0.f, v3 = 0.f;
        #pragma unroll 4
        for (int m2 = m0; m2 < m0 + MM / 2; m2 += 4) {
            v0 = fmaf(sacc[m2],     g_W2c[m2 * MM + col],       v0);
            v1 = fmaf(sacc[m2 + 1], g_W2c[(m2 + 1) * MM + col], v1);
            v2 = fmaf(sacc[m2 + 2], g_W2c[(m2 + 2) * MM + col], v2);
            v3 = fmaf(sacc[m2 + 3], g_W2c[(m2 + 3) * MM + col], v3);
        }
        parts[half][col] = (v0 + v1) + (v2 + v3);
    }
    __syncthreads();
    if (t < MM) {
        float u = fmaf(parts[0][t] + parts[1][t] + S * g_b2c[t], inv_d, bc1[t]);
        shid[t] = siluf(u);
    }
    __syncthreads();

    {
        float v0 = (half == 0) ? bc2[col] : 0.0f, v1 = 0.f, v2 = 0.f, v3 = 0.f;
        #pragma unroll 4
        for (int m2 = m0; m2 < m0 + MM / 2; m2 += 4) {
            v0 = fmaf(shid[m2],     Wc2[m2 * CC + col],       v0);
            v1 = fmaf(shid[m2 + 1], Wc2[(m2 + 1) * CC + col], v1);
            v2 = fmaf(shid[m2 + 2], Wc2[(m2 + 2) * CC + col], v2);
            v3 = fmaf(shid[m2 + 3], Wc2[(m2 + 3) * CC + col], v3);
        }
        parts[half][col] = (v0 + v1) + (v2 + v3);
    }
    __syncthreads();
    if (t < CC) out[(size_t)bi * CC + t] = parts[0][t] + parts[1][t];
}

// ---------------------------------------------------------------------------
// Launch
// ---------------------------------------------------------------------------
extern "C" void kernel_launch(void* const* d_in, const int* in_sizes, int n_in,
                              void* d_out, int out_size)
{
    const float* h   = (const float*)d_in[0];
    const float* adj = (const float*)d_in[1];
    const float* W1a = (const float*)d_in[2];
    const float* W1b = (const float*)d_in[3];
    const float* b1  = (const float*)d_in[4];
    const float* W2  = (const float*)d_in[5];
    const float* b2  = (const float*)d_in[6];
    const float* Wc1 = (const float*)d_in[7];
    const float* bc1 = (const float*)d_in[8];
    const float* Wc2 = (const float*)d_in[9];
    const float* bc2 = (const float*)d_in[10];
    float* out = (float*)d_out;

    prep_kernel<<<321, 256>>>(h, W1a, W1b, b1, W2, b2, Wc1);
    main_kernel<<<BB * NN, 256>>>(adj, bc1, Wc2, bc2, out);
}